// round 15
// baseline (speedup 1.0000x reference)
#include <cuda_runtime.h>
#include <cuda_bf16.h>

// Problem constants (fixed shapes per reference setup_inputs)
#define D 512
#define T 50000
#define K 16
#define N_ITERS 10

// Heavy-kernel tiling
#define HK_THREADS 256
#define CPT 4                       // columns per thread (2x f32x2 accumulators)
#define TILE_COLS (HK_THREADS*CPT)  // 1024
#define NTILE 49                    // ceil(50000/1024)
#define CHUNK_ROWS 64
#define NCHUNK 8                    // 8*64 = 512 rows
#define ROWS_REG 4                  // rows held in registers per inner block
#define NRB (CHUNK_ROWS/ROWS_REG)   // 16 row-blocks
#define GRID_BLOCKS (NTILE*NCHUNK)  // 392

// Reference hyper-parameters
#define LAMBDA1_F 0.3366f
#define SHRINK_C ((float)(0.1 * 0.3366))        // LR*LAMBDA1
#define BETA1_F 0.9f
#define BETA2_F 0.999f
#define ONE_M_B1 ((float)(1.0 - 0.9))
#define ONE_M_B2 ((float)(1.0 - 0.999))
#define ADAM_EPS_F 1e-8f
#define LR_F 0.1f

#define ABS2_MASK 0x7FFFFFFF7FFFFFFFull

// Device-global scratch (no allocations allowed)
__device__ float g_B[D * K];      // B the loss sees (P for it=1, shrink(P) after)
__device__ float g_P[D * K];
__device__ float g_M[D * K];
__device__ float g_V[D * K];
__device__ float g_colsum[(N_ITERS + 1) * T];     // per-iteration colsum slices (RED targets)
__device__ __nv_bfloat16 g_Ebf[(size_t)D * T];    // bf16 copy of E (iters 2..N)
__device__ unsigned int g_count[N_ITERS + 1];

// ---------- f32x2 helpers ----------
__device__ __forceinline__ unsigned long long fma2(unsigned long long a,
                                                   unsigned long long b,
                                                   unsigned long long c) {
    unsigned long long d;
    asm("fma.rn.f32x2 %0, %1, %2, %3;" : "=l"(d) : "l"(a), "l"(b), "l"(c));
    return d;
}
__device__ __forceinline__ unsigned long long add2(unsigned long long a,
                                                   unsigned long long b) {
    unsigned long long d;
    asm("add.rn.f32x2 %0, %1, %2;" : "=l"(d) : "l"(a), "l"(b));
    return d;
}
__device__ __forceinline__ float f2lo(unsigned long long x) {
    return __uint_as_float((unsigned int)x);
}
__device__ __forceinline__ float f2hi(unsigned long long x) {
    return __uint_as_float((unsigned int)(x >> 32));
}
__device__ __forceinline__ unsigned long long packf2(float lo, float hi) {
    return ((unsigned long long)__float_as_uint(hi) << 32) |
           (unsigned long long)__float_as_uint(lo);
}
// bf16x2 (lo=col j, hi=col j+1) -> packed f32x2 via 2x PRMT
__device__ __forceinline__ unsigned long long bf2_to_f2(unsigned int u) {
    unsigned int lo = __byte_perm(u, 0, 0x1044);   // bf_lo << 16
    unsigned int hi = __byte_perm(u, 0, 0x3244);   // bf_hi << 16
    return ((unsigned long long)hi << 32) | lo;
}
__device__ __forceinline__ float sgnf(float x) {
    return (float)((x > 0.0f) - (x < 0.0f));
}

// ---------- init: zero colsum slices + counters, seed optimizer state ----------
__global__ void init_kernel(const float* __restrict__ Binit) {
    int i = blockIdx.x * blockDim.x + threadIdx.x;
    // zero g_colsum via float4 grid-stride
    float4 z = make_float4(0.f, 0.f, 0.f, 0.f);
    const int n4 = (N_ITERS + 1) * T / 4;   // 550000/4 divisible
    for (int v = i; v < n4; v += gridDim.x * blockDim.x)
        reinterpret_cast<float4*>(g_colsum)[v] = z;
    if (i <= N_ITERS) g_count[i] = 0u;
    if (i < D * K) {
        float b = Binit[i];
        g_P[i] = b;
        g_B[i] = b;     // iteration 1 loss sees raw P
        g_M[i] = 0.0f;
        g_V[i] = 0.0f;
    }
}

// ---------- fused heavy + argmax + update ----------
// FIRST=true: reads fp32 E, also writes bf16 copy. FIRST=false: reads bf16 copy.
template <bool FIRST>
__global__ __launch_bounds__(HK_THREADS, 2)
void heavy_kernel(const float* __restrict__ E, const float* __restrict__ A,
                  float* __restrict__ outB, int it) {
    // Bt[k][r]: -B[chunk*64+r][k], lane-duplicated into both f32x2 halves (8 KB)
    __shared__ unsigned long long sBt[K * CHUNK_ROWS];
    __shared__ unsigned long long s_wmax[HK_THREADS / 32];
    __shared__ float sA[K];
    __shared__ float sColabs[K];
    __shared__ int sJstar, sKstar, sIsLast;

    const int tile = blockIdx.x;
    const int chunk = blockIdx.y;
    const int tid = threadIdx.x;

    for (int idx = tid; idx < K * CHUNK_ROWS; idx += HK_THREADS) {
        int k = idx & (K - 1);
        int r = idx >> 4;
        float b = -g_B[(chunk * CHUNK_ROWS + r) * K + k];
        unsigned int ub = __float_as_uint(b);
        sBt[k * CHUNK_ROWS + r] = ((unsigned long long)ub << 32) | (unsigned long long)ub;
    }
    __syncthreads();

    const int j0 = tile * TILE_COLS + tid * CPT;
    const int row0 = chunk * CHUNK_ROWS;

    if (j0 < T) {
        // A[k, j0..j0+3] into registers (fp32, 16B aligned)
        unsigned long long a01[K], a23[K];
#pragma unroll
        for (int k = 0; k < K; k++) {
            ulonglong2 av = *reinterpret_cast<const ulonglong2*>(A + k * T + j0);
            a01[k] = av.x;
            a23[k] = av.y;
        }

        unsigned long long cs01 = 0ull, cs23 = 0ull;

        if (FIRST) {
            const float* ep = E + (long long)row0 * T + j0;
            __nv_bfloat16* bp_out = g_Ebf + (long long)row0 * T + j0;
#pragma unroll 1
            for (int rb = 0; rb < NRB; rb++) {
                unsigned long long acc01[ROWS_REG], acc23[ROWS_REG];
#pragma unroll
                for (int r = 0; r < ROWS_REG; r++) {
                    float4 ev = *reinterpret_cast<const float4*>(ep + r * T);
                    acc01[r] = packf2(ev.x, ev.y);
                    acc23[r] = packf2(ev.z, ev.w);
                    unsigned int p01, p23;
                    asm("cvt.rn.bf16x2.f32 %0, %1, %2;" : "=r"(p01) : "f"(ev.y), "f"(ev.x));
                    asm("cvt.rn.bf16x2.f32 %0, %1, %2;" : "=r"(p23) : "f"(ev.w), "f"(ev.z));
                    uint2 st; st.x = p01; st.y = p23;
                    *reinterpret_cast<uint2*>(bp_out + r * T) = st;
                }
                ep += ROWS_REG * T;
                bp_out += ROWS_REG * T;

                const unsigned long long* bb = &sBt[rb * ROWS_REG];
                ulonglong2 b01 = *reinterpret_cast<const ulonglong2*>(bb);
                ulonglong2 b23 = *reinterpret_cast<const ulonglong2*>(bb + 2);
#pragma unroll
                for (int k = 0; k < K; k++) {
                    ulonglong2 nb01, nb23;
                    if (k + 1 < K) {
                        nb01 = *reinterpret_cast<const ulonglong2*>(bb + (k + 1) * CHUNK_ROWS);
                        nb23 = *reinterpret_cast<const ulonglong2*>(bb + (k + 1) * CHUNK_ROWS + 2);
                    }
                    acc01[0] = fma2(b01.x, a01[k], acc01[0]);
                    acc23[0] = fma2(b01.x, a23[k], acc23[0]);
                    acc01[1] = fma2(b01.y, a01[k], acc01[1]);
                    acc23[1] = fma2(b01.y, a23[k], acc23[1]);
                    acc01[2] = fma2(b23.x, a01[k], acc01[2]);
                    acc23[2] = fma2(b23.x, a23[k], acc23[2]);
                    acc01[3] = fma2(b23.y, a01[k], acc01[3]);
                    acc23[3] = fma2(b23.y, a23[k], acc23[3]);
                    b01 = nb01; b23 = nb23;
                }
#pragma unroll
                for (int r = 0; r < ROWS_REG; r++) {
                    cs01 = add2(cs01, acc01[r] & ABS2_MASK);
                    cs23 = add2(cs23, acc23[r] & ABS2_MASK);
                }
            }
        } else {
            const __nv_bfloat16* ep = g_Ebf + (long long)row0 * T + j0;
            uint2 e[ROWS_REG], en[ROWS_REG];
#pragma unroll
            for (int r = 0; r < ROWS_REG; r++)
                e[r] = *reinterpret_cast<const uint2*>(ep + r * T);

#pragma unroll 1
            for (int rb = 0; rb < NRB; rb++) {
                if (rb + 1 < NRB) {
                    const __nv_bfloat16* epn = ep + ROWS_REG * T;
#pragma unroll
                    for (int r = 0; r < ROWS_REG; r++)
                        en[r] = *reinterpret_cast<const uint2*>(epn + r * T);
                }
                ep += ROWS_REG * T;

                unsigned long long acc01[ROWS_REG], acc23[ROWS_REG];
#pragma unroll
                for (int r = 0; r < ROWS_REG; r++) {
                    acc01[r] = bf2_to_f2(e[r].x);
                    acc23[r] = bf2_to_f2(e[r].y);
                }
                const unsigned long long* bb = &sBt[rb * ROWS_REG];
                ulonglong2 b01 = *reinterpret_cast<const ulonglong2*>(bb);
                ulonglong2 b23 = *reinterpret_cast<const ulonglong2*>(bb + 2);
#pragma unroll
                for (int k = 0; k < K; k++) {
                    ulonglong2 nb01, nb23;
                    if (k + 1 < K) {
                        nb01 = *reinterpret_cast<const ulonglong2*>(bb + (k + 1) * CHUNK_ROWS);
                        nb23 = *reinterpret_cast<const ulonglong2*>(bb + (k + 1) * CHUNK_ROWS + 2);
                    }
                    acc01[0] = fma2(b01.x, a01[k], acc01[0]);
                    acc23[0] = fma2(b01.x, a23[k], acc23[0]);
                    acc01[1] = fma2(b01.y, a01[k], acc01[1]);
                    acc23[1] = fma2(b01.y, a23[k], acc23[1]);
                    acc01[2] = fma2(b23.x, a01[k], acc01[2]);
                    acc23[2] = fma2(b23.x, a23[k], acc23[2]);
                    acc01[3] = fma2(b23.y, a01[k], acc01[3]);
                    acc23[3] = fma2(b23.y, a23[k], acc23[3]);
                    b01 = nb01; b23 = nb23;
                }
#pragma unroll
                for (int r = 0; r < ROWS_REG; r++) {
                    cs01 = add2(cs01, acc01[r] & ABS2_MASK);
                    cs23 = add2(cs23, acc23[r] & ABS2_MASK);
                    e[r] = en[r];
                }
            }
        }

        // accumulate into this iteration's colsum slice (RED.F32, no return)
        float* csl = g_colsum + it * T + j0;
        atomicAdd(csl + 0, f2lo(cs01));
        atomicAdd(csl + 1, f2hi(cs01));
        atomicAdd(csl + 2, f2lo(cs23));
        atomicAdd(csl + 3, f2hi(cs23));
    }

    // ---------- last-block epilogue (threadfence-reduction pattern) ----------
    __threadfence();
    __syncthreads();
    if (tid == 0) {
        unsigned int ticket = atomicAdd(&g_count[it], 1u);
        sIsLast = (ticket == GRID_BLOCKS - 1);
    }
    __syncthreads();
    if (!sIsLast) return;

    // argmax over colsum slice (float4, coalesced)
    {
        const float4* cs4 = reinterpret_cast<const float4*>(g_colsum + it * T);
        unsigned long long best = 0ull;
        for (int v = tid; v < T / 4; v += HK_THREADS) {
            float4 val = cs4[v];
            int j = 4 * v;
            // values >= 0 -> float bits order-preserving; tie-break toward smaller j
            unsigned long long k0 =
                ((unsigned long long)__float_as_uint(val.x) << 32) | (unsigned int)(T - 1 - j);
            unsigned long long k1 =
                ((unsigned long long)__float_as_uint(val.y) << 32) | (unsigned int)(T - 2 - j);
            unsigned long long k2 =
                ((unsigned long long)__float_as_uint(val.z) << 32) | (unsigned int)(T - 3 - j);
            unsigned long long k3 =
                ((unsigned long long)__float_as_uint(val.w) << 32) | (unsigned int)(T - 4 - j);
            if (k1 > k0) k0 = k1;
            if (k3 > k2) k2 = k3;
            if (k2 > k0) k0 = k2;
            if (k0 > best) best = k0;
        }
#pragma unroll
        for (int o = 16; o; o >>= 1) {
            unsigned long long other = __shfl_down_sync(0xffffffffu, best, o);
            if (other > best) best = other;
        }
        if ((tid & 31) == 0) s_wmax[tid >> 5] = best;
        __syncthreads();
        if (tid == 0) {
            unsigned long long b = s_wmax[0];
#pragma unroll
            for (int w = 1; w < HK_THREADS / 32; w++)
                if (s_wmax[w] > b) b = s_wmax[w];
            sJstar = T - 1 - (int)(b & 0xffffffffu);
        }
        __syncthreads();
    }
    const int jstar = sJstar;

    // stage A[:, j*]
    if (tid < K) sA[tid] = A[tid * T + jstar];

    // column abs-sums of B: warp w handles columns w and w+8
    {
        int w = tid >> 5, lane = tid & 31;
#pragma unroll
        for (int c = w; c < K; c += HK_THREADS / 32) {
            float s = 0.0f;
            for (int i = lane; i < D; i += 32) s += fabsf(g_B[i * K + c]);
#pragma unroll
            for (int o = 16; o; o >>= 1) s += __shfl_down_sync(0xffffffffu, s, o);
            if (lane == 0) sColabs[c] = s;
        }
    }
    __syncthreads();
    if (tid == 0) {
        int ks = 0;
        float bv = sColabs[0];
#pragma unroll
        for (int k = 1; k < K; k++)
            if (sColabs[k] > bv) { bv = sColabs[k]; ks = k; }
        sKstar = ks;
    }

    // residual sign for rows tid, tid+256 at column j* (exact fp32 from original E)
    float si[2];
#pragma unroll
    for (int h = 0; h < 2; h++) {
        int row = tid + h * HK_THREADS;
        float r = E[(long long)row * T + jstar];
#pragma unroll
        for (int k = 0; k < K; k++) r -= g_B[row * K + k] * sA[k];
        si[h] = sgnf(r);
    }
    __syncthreads();            // sKstar ready; g_B reads complete before writes
    const int kstar = sKstar;

    // gradient + shrink chain + Adam + new B = shrink(P)
    {
        float tf = (float)it;
        float bc1 = 1.0f - powf(BETA1_F, tf);
        float bc2 = 1.0f - powf(BETA2_F, tf);
#pragma unroll
        for (int h = 0; h < 2; h++) {
            int row = tid + h * HK_THREADS;
#pragma unroll
            for (int k = 0; k < K; k++) {
                int idx = row * K + k;
                float bu = g_B[idx];
                float g = -si[h] * sA[k];
                if (k == kstar) g += LAMBDA1_F * sgnf(bu);
                float p = g_P[idx];
                if (it >= 2) g *= sgnf(p) * sgnf(p - SHRINK_C);   // d shrink / dP
                float m = BETA1_F * g_M[idx] + ONE_M_B1 * g;
                float v = BETA2_F * g_V[idx] + ONE_M_B2 * g * g;
                g_M[idx] = m;
                g_V[idx] = v;
                float mh = m / bc1;
                float vh = v / bc2;
                p = p - LR_F * mh / (sqrtf(vh) + ADAM_EPS_F);
                g_P[idx] = p;
                float bn = sgnf(p) * fmaxf(0.0f, fabsf(p - SHRINK_C));
                g_B[idx] = bn;
                if (it == N_ITERS) outB[idx] = bn;
            }
        }
    }
}

extern "C" void kernel_launch(void* const* d_in, const int* in_sizes, int n_in,
                              void* d_out, int out_size) {
    (void)in_sizes; (void)n_in; (void)out_size;
    const float* E  = (const float*)d_in[0];   // embedding (512, 50000)
    const float* B0 = (const float*)d_in[1];   // basis_init (512, 16)
    const float* A  = (const float*)d_in[2];   // activation_init (16, 50000)
    float* out = (float*)d_out;                // [shrink(P) (512x16) | A (16x50000)]

    // A is constant in the reference (optimizer_act never steps) — copy once
    cudaMemcpyAsync(out + D * K, (const void*)A, (size_t)K * T * sizeof(float),
                    cudaMemcpyDeviceToDevice);

    init_kernel<<<592, 256>>>(B0);   // 592*256 threads: zeroes 137.5K float4 in one stride

    dim3 grid(NTILE, NCHUNK);
    for (int it = 1; it <= N_ITERS; ++it) {
        if (it == 1)
            heavy_kernel<true><<<grid, HK_THREADS>>>(E, A, out, it);
        else
            heavy_kernel<false><<<grid, HK_THREADS>>>(E, A, out, it);
    }
}

// round 16
// speedup vs baseline: 1.0060x; 1.0060x over previous
#include <cuda_runtime.h>
#include <cuda_bf16.h>

// Problem constants (fixed shapes per reference setup_inputs)
#define D 512
#define T 50000
#define K 16
#define N_ITERS 10

// Heavy-kernel tiling
#define HK_THREADS 256
#define CPT 4                       // columns per thread (2x f32x2 accumulators)
#define TILE_COLS (HK_THREADS*CPT)  // 1024
#define NTILE 49                    // ceil(50000/1024)
#define CHUNK_ROWS 64
#define NCHUNK 8                    // 8*64 = 512 rows
#define ROWS_REG 4                  // rows held in registers per inner block
#define NRB (CHUNK_ROWS/ROWS_REG)   // 16 row-blocks
#define GRID_BLOCKS (NTILE*NCHUNK)  // 392

// Reference hyper-parameters
#define LAMBDA1_F 0.3366f
#define SHRINK_C ((float)(0.1 * 0.3366))        // LR*LAMBDA1
#define BETA1_F 0.9f
#define BETA2_F 0.999f
#define ONE_M_B1 ((float)(1.0 - 0.9))
#define ONE_M_B2 ((float)(1.0 - 0.999))
#define ADAM_EPS_F 1e-8f
#define LR_F 0.1f

#define ABS2_MASK 0x7FFFFFFF7FFFFFFFull

// Device-global scratch (no allocations allowed)
__device__ float g_B[D * K];      // B the loss sees (P for it=1, shrink(P) after)
__device__ float g_P[D * K];
__device__ float g_M[D * K];
__device__ float g_V[D * K];
__device__ float g_colsum[(N_ITERS + 1) * T];     // per-iteration colsum slices (RED targets)
__device__ __nv_bfloat16 g_Ebf[(size_t)D * T];    // bf16 copy of E (iters 2..N)
__device__ unsigned int g_count[N_ITERS + 1];

// ---------- f32x2 helpers ----------
__device__ __forceinline__ unsigned long long fma2(unsigned long long a,
                                                   unsigned long long b,
                                                   unsigned long long c) {
    unsigned long long d;
    asm("fma.rn.f32x2 %0, %1, %2, %3;" : "=l"(d) : "l"(a), "l"(b), "l"(c));
    return d;
}
__device__ __forceinline__ unsigned long long add2(unsigned long long a,
                                                   unsigned long long b) {
    unsigned long long d;
    asm("add.rn.f32x2 %0, %1, %2;" : "=l"(d) : "l"(a), "l"(b));
    return d;
}
__device__ __forceinline__ float f2lo(unsigned long long x) {
    return __uint_as_float((unsigned int)x);
}
__device__ __forceinline__ float f2hi(unsigned long long x) {
    return __uint_as_float((unsigned int)(x >> 32));
}
__device__ __forceinline__ unsigned long long packf2(float lo, float hi) {
    return ((unsigned long long)__float_as_uint(hi) << 32) |
           (unsigned long long)__float_as_uint(lo);
}
// bf16x2 (lo=col j, hi=col j+1) -> packed f32x2 via 2x PRMT
__device__ __forceinline__ unsigned long long bf2_to_f2(unsigned int u) {
    unsigned int lo = __byte_perm(u, 0, 0x1044);   // bf_lo << 16
    unsigned int hi = __byte_perm(u, 0, 0x3244);   // bf_hi << 16
    return ((unsigned long long)hi << 32) | lo;
}
__device__ __forceinline__ float sgnf(float x) {
    return (float)((x > 0.0f) - (x < 0.0f));
}

// ---------- init: zero colsum slices + counters, seed optimizer state ----------
__global__ void init_kernel(const float* __restrict__ Binit) {
    int i = blockIdx.x * blockDim.x + threadIdx.x;
    // zero g_colsum via float4 grid-stride
    float4 z = make_float4(0.f, 0.f, 0.f, 0.f);
    const int n4 = (N_ITERS + 1) * T / 4;   // 550000/4 divisible
    for (int v = i; v < n4; v += gridDim.x * blockDim.x)
        reinterpret_cast<float4*>(g_colsum)[v] = z;
    if (i <= N_ITERS) g_count[i] = 0u;
    if (i < D * K) {
        float b = Binit[i];
        g_P[i] = b;
        g_B[i] = b;     // iteration 1 loss sees raw P
        g_M[i] = 0.0f;
        g_V[i] = 0.0f;
    }
}

// ---------- fused heavy + argmax + update ----------
// FIRST=true: reads fp32 E, also writes bf16 copy. FIRST=false: reads bf16 copy.
template <bool FIRST>
__global__ __launch_bounds__(HK_THREADS, 2)
void heavy_kernel(const float* __restrict__ E, const float* __restrict__ A,
                  float* __restrict__ outB, int it) {
    // Bt[k][r]: -B[chunk*64+r][k], lane-duplicated into both f32x2 halves (8 KB)
    __shared__ unsigned long long sBt[K * CHUNK_ROWS];
    __shared__ unsigned long long s_wmax[HK_THREADS / 32];
    __shared__ float sA[K];
    __shared__ float sColabs[K];
    __shared__ int sJstar, sKstar, sIsLast;

    const int tile = blockIdx.x;
    const int chunk = blockIdx.y;
    const int tid = threadIdx.x;

    for (int idx = tid; idx < K * CHUNK_ROWS; idx += HK_THREADS) {
        int k = idx & (K - 1);
        int r = idx >> 4;
        float b = -g_B[(chunk * CHUNK_ROWS + r) * K + k];
        unsigned int ub = __float_as_uint(b);
        sBt[k * CHUNK_ROWS + r] = ((unsigned long long)ub << 32) | (unsigned long long)ub;
    }
    __syncthreads();

    const int j0 = tile * TILE_COLS + tid * CPT;
    const int row0 = chunk * CHUNK_ROWS;

    if (j0 < T) {
        // A[k, j0..j0+3] into registers (fp32, 16B aligned)
        unsigned long long a01[K], a23[K];
#pragma unroll
        for (int k = 0; k < K; k++) {
            ulonglong2 av = *reinterpret_cast<const ulonglong2*>(A + k * T + j0);
            a01[k] = av.x;
            a23[k] = av.y;
        }

        unsigned long long cs01 = 0ull, cs23 = 0ull;

        if (FIRST) {
            const float* ep = E + (long long)row0 * T + j0;
            __nv_bfloat16* bp_out = g_Ebf + (long long)row0 * T + j0;
#pragma unroll 1
            for (int rb = 0; rb < NRB; rb++) {
                unsigned long long acc01[ROWS_REG], acc23[ROWS_REG];
#pragma unroll
                for (int r = 0; r < ROWS_REG; r++) {
                    float4 ev = *reinterpret_cast<const float4*>(ep + r * T);
                    acc01[r] = packf2(ev.x, ev.y);
                    acc23[r] = packf2(ev.z, ev.w);
                    unsigned int p01, p23;
                    asm("cvt.rn.bf16x2.f32 %0, %1, %2;" : "=r"(p01) : "f"(ev.y), "f"(ev.x));
                    asm("cvt.rn.bf16x2.f32 %0, %1, %2;" : "=r"(p23) : "f"(ev.w), "f"(ev.z));
                    uint2 st; st.x = p01; st.y = p23;
                    *reinterpret_cast<uint2*>(bp_out + r * T) = st;
                }
                ep += ROWS_REG * T;
                bp_out += ROWS_REG * T;

                const unsigned long long* bb = &sBt[rb * ROWS_REG];
                ulonglong2 b01 = *reinterpret_cast<const ulonglong2*>(bb);
                ulonglong2 b23 = *reinterpret_cast<const ulonglong2*>(bb + 2);
#pragma unroll
                for (int k = 0; k < K; k++) {
                    ulonglong2 nb01, nb23;
                    if (k + 1 < K) {
                        nb01 = *reinterpret_cast<const ulonglong2*>(bb + (k + 1) * CHUNK_ROWS);
                        nb23 = *reinterpret_cast<const ulonglong2*>(bb + (k + 1) * CHUNK_ROWS + 2);
                    }
                    acc01[0] = fma2(b01.x, a01[k], acc01[0]);
                    acc23[0] = fma2(b01.x, a23[k], acc23[0]);
                    acc01[1] = fma2(b01.y, a01[k], acc01[1]);
                    acc23[1] = fma2(b01.y, a23[k], acc23[1]);
                    acc01[2] = fma2(b23.x, a01[k], acc01[2]);
                    acc23[2] = fma2(b23.x, a23[k], acc23[2]);
                    acc01[3] = fma2(b23.y, a01[k], acc01[3]);
                    acc23[3] = fma2(b23.y, a23[k], acc23[3]);
                    b01 = nb01; b23 = nb23;
                }
#pragma unroll
                for (int r = 0; r < ROWS_REG; r++) {
                    cs01 = add2(cs01, acc01[r] & ABS2_MASK);
                    cs23 = add2(cs23, acc23[r] & ABS2_MASK);
                }
            }
        } else {
            const __nv_bfloat16* ep = g_Ebf + (long long)row0 * T + j0;
            uint2 e[ROWS_REG], en[ROWS_REG];
#pragma unroll
            for (int r = 0; r < ROWS_REG; r++)
                e[r] = *reinterpret_cast<const uint2*>(ep + r * T);

#pragma unroll 1
            for (int rb = 0; rb < NRB; rb++) {
                if (rb + 1 < NRB) {
                    const __nv_bfloat16* epn = ep + ROWS_REG * T;
#pragma unroll
                    for (int r = 0; r < ROWS_REG; r++)
                        en[r] = *reinterpret_cast<const uint2*>(epn + r * T);
                }
                ep += ROWS_REG * T;

                unsigned long long acc01[ROWS_REG], acc23[ROWS_REG];
#pragma unroll
                for (int r = 0; r < ROWS_REG; r++) {
                    acc01[r] = bf2_to_f2(e[r].x);
                    acc23[r] = bf2_to_f2(e[r].y);
                }
                const unsigned long long* bb = &sBt[rb * ROWS_REG];
                ulonglong2 b01 = *reinterpret_cast<const ulonglong2*>(bb);
                ulonglong2 b23 = *reinterpret_cast<const ulonglong2*>(bb + 2);
#pragma unroll
                for (int k = 0; k < K; k++) {
                    ulonglong2 nb01, nb23;
                    if (k + 1 < K) {
                        nb01 = *reinterpret_cast<const ulonglong2*>(bb + (k + 1) * CHUNK_ROWS);
                        nb23 = *reinterpret_cast<const ulonglong2*>(bb + (k + 1) * CHUNK_ROWS + 2);
                    }
                    acc01[0] = fma2(b01.x, a01[k], acc01[0]);
                    acc23[0] = fma2(b01.x, a23[k], acc23[0]);
                    acc01[1] = fma2(b01.y, a01[k], acc01[1]);
                    acc23[1] = fma2(b01.y, a23[k], acc23[1]);
                    acc01[2] = fma2(b23.x, a01[k], acc01[2]);
                    acc23[2] = fma2(b23.x, a23[k], acc23[2]);
                    acc01[3] = fma2(b23.y, a01[k], acc01[3]);
                    acc23[3] = fma2(b23.y, a23[k], acc23[3]);
                    b01 = nb01; b23 = nb23;
                }
#pragma unroll
                for (int r = 0; r < ROWS_REG; r++) {
                    cs01 = add2(cs01, acc01[r] & ABS2_MASK);
                    cs23 = add2(cs23, acc23[r] & ABS2_MASK);
                    e[r] = en[r];
                }
            }
        }

        // accumulate into this iteration's colsum slice (RED.F32, no return)
        float* csl = g_colsum + it * T + j0;
        atomicAdd(csl + 0, f2lo(cs01));
        atomicAdd(csl + 1, f2hi(cs01));
        atomicAdd(csl + 2, f2lo(cs23));
        atomicAdd(csl + 3, f2hi(cs23));
    }

    // ---------- last-block epilogue (threadfence-reduction pattern) ----------
    __threadfence();
    __syncthreads();
    if (tid == 0) {
        unsigned int ticket = atomicAdd(&g_count[it], 1u);
        sIsLast = (ticket == GRID_BLOCKS - 1);
    }
    __syncthreads();
    if (!sIsLast) return;

    // argmax over colsum slice (float4, coalesced)
    {
        const float4* cs4 = reinterpret_cast<const float4*>(g_colsum + it * T);
        unsigned long long best = 0ull;
        for (int v = tid; v < T / 4; v += HK_THREADS) {
            float4 val = cs4[v];
            int j = 4 * v;
            // values >= 0 -> float bits order-preserving; tie-break toward smaller j
            unsigned long long k0 =
                ((unsigned long long)__float_as_uint(val.x) << 32) | (unsigned int)(T - 1 - j);
            unsigned long long k1 =
                ((unsigned long long)__float_as_uint(val.y) << 32) | (unsigned int)(T - 2 - j);
            unsigned long long k2 =
                ((unsigned long long)__float_as_uint(val.z) << 32) | (unsigned int)(T - 3 - j);
            unsigned long long k3 =
                ((unsigned long long)__float_as_uint(val.w) << 32) | (unsigned int)(T - 4 - j);
            if (k1 > k0) k0 = k1;
            if (k3 > k2) k2 = k3;
            if (k2 > k0) k0 = k2;
            if (k0 > best) best = k0;
        }
#pragma unroll
        for (int o = 16; o; o >>= 1) {
            unsigned long long other = __shfl_down_sync(0xffffffffu, best, o);
            if (other > best) best = other;
        }
        if ((tid & 31) == 0) s_wmax[tid >> 5] = best;
        __syncthreads();
        if (tid == 0) {
            unsigned long long b = s_wmax[0];
#pragma unroll
            for (int w = 1; w < HK_THREADS / 32; w++)
                if (s_wmax[w] > b) b = s_wmax[w];
            sJstar = T - 1 - (int)(b & 0xffffffffu);
        }
        __syncthreads();
    }
    const int jstar = sJstar;

    // stage A[:, j*]
    if (tid < K) sA[tid] = A[tid * T + jstar];

    // column abs-sums of B: warp w handles columns w and w+8
    {
        int w = tid >> 5, lane = tid & 31;
#pragma unroll
        for (int c = w; c < K; c += HK_THREADS / 32) {
            float s = 0.0f;
            for (int i = lane; i < D; i += 32) s += fabsf(g_B[i * K + c]);
#pragma unroll
            for (int o = 16; o; o >>= 1) s += __shfl_down_sync(0xffffffffu, s, o);
            if (lane == 0) sColabs[c] = s;
        }
    }
    __syncthreads();
    if (tid == 0) {
        int ks = 0;
        float bv = sColabs[0];
#pragma unroll
        for (int k = 1; k < K; k++)
            if (sColabs[k] > bv) { bv = sColabs[k]; ks = k; }
        sKstar = ks;
    }

    // residual sign for rows tid, tid+256 at column j* (exact fp32 from original E)
    float si[2];
#pragma unroll
    for (int h = 0; h < 2; h++) {
        int row = tid + h * HK_THREADS;
        float r = E[(long long)row * T + jstar];
#pragma unroll
        for (int k = 0; k < K; k++) r -= g_B[row * K + k] * sA[k];
        si[h] = sgnf(r);
    }
    __syncthreads();            // sKstar ready; g_B reads complete before writes
    const int kstar = sKstar;

    // gradient + shrink chain + Adam + new B = shrink(P)
    {
        float tf = (float)it;
        float bc1 = 1.0f - powf(BETA1_F, tf);
        float bc2 = 1.0f - powf(BETA2_F, tf);
#pragma unroll
        for (int h = 0; h < 2; h++) {
            int row = tid + h * HK_THREADS;
#pragma unroll
            for (int k = 0; k < K; k++) {
                int idx = row * K + k;
                float bu = g_B[idx];
                float g = -si[h] * sA[k];
                if (k == kstar) g += LAMBDA1_F * sgnf(bu);
                float p = g_P[idx];
                if (it >= 2) g *= sgnf(p) * sgnf(p - SHRINK_C);   // d shrink / dP
                float m = BETA1_F * g_M[idx] + ONE_M_B1 * g;
                float v = BETA2_F * g_V[idx] + ONE_M_B2 * g * g;
                g_M[idx] = m;
                g_V[idx] = v;
                float mh = m / bc1;
                float vh = v / bc2;
                p = p - LR_F * mh / (sqrtf(vh) + ADAM_EPS_F);
                g_P[idx] = p;
                float bn = sgnf(p) * fmaxf(0.0f, fabsf(p - SHRINK_C));
                g_B[idx] = bn;
                if (it == N_ITERS) outB[idx] = bn;
            }
        }
    }
}

extern "C" void kernel_launch(void* const* d_in, const int* in_sizes, int n_in,
                              void* d_out, int out_size) {
    (void)in_sizes; (void)n_in; (void)out_size;
    const float* E  = (const float*)d_in[0];   // embedding (512, 50000)
    const float* B0 = (const float*)d_in[1];   // basis_init (512, 16)
    const float* A  = (const float*)d_in[2];   // activation_init (16, 50000)
    float* out = (float*)d_out;                // [shrink(P) (512x16) | A (16x50000)]

    // A is constant in the reference (optimizer_act never steps) — copy once
    cudaMemcpyAsync(out + D * K, (const void*)A, (size_t)K * T * sizeof(float),
                    cudaMemcpyDeviceToDevice);

    init_kernel<<<592, 256>>>(B0);   // 592*256 threads: zeroes 137.5K float4 in one stride

    dim3 grid(NTILE, NCHUNK);
    for (int it = 1; it <= N_ITERS; ++it) {
        if (it == 1)
            heavy_kernel<true><<<grid, HK_THREADS>>>(E, A, out, it);
        else
            heavy_kernel<false><<<grid, HK_THREADS>>>(E, A, out, it);
    }
}

// round 17
// speedup vs baseline: 1.0062x; 1.0003x over previous
#include <cuda_runtime.h>
#include <cuda_bf16.h>

// Problem constants (fixed shapes per reference setup_inputs)
#define D 512
#define T 50000
#define K 16
#define N_ITERS 10

// Heavy-kernel tiling
#define HK_THREADS 256
#define CPT 4                       // columns per thread (2x f32x2 accumulators)
#define TILE_COLS (HK_THREADS*CPT)  // 1024
#define NTILE 49                    // ceil(50000/1024)
#define CHUNK_ROWS 64
#define NCHUNK 8                    // 8*64 = 512 rows
#define ROWS_REG 4                  // rows held in registers per inner block
#define NRB (CHUNK_ROWS/ROWS_REG)   // 16 row-blocks
#define GRID_BLOCKS (NTILE*NCHUNK)  // 392

// Reference hyper-parameters
#define LAMBDA1_F 0.3366f
#define SHRINK_C ((float)(0.1 * 0.3366))        // LR*LAMBDA1
#define BETA1_F 0.9f
#define BETA2_F 0.999f
#define ONE_M_B1 ((float)(1.0 - 0.9))
#define ONE_M_B2 ((float)(1.0 - 0.999))
#define ADAM_EPS_F 1e-8f
#define LR_F 0.1f

#define ABS2_MASK 0x7FFFFFFF7FFFFFFFull

// Device-global scratch (no allocations allowed)
__device__ float g_B[D * K];      // B the loss sees (P for it=1, shrink(P) after)
__device__ float g_P[D * K];
__device__ float g_M[D * K];
__device__ float g_V[D * K];
__device__ float g_colsum[(N_ITERS + 1) * T];     // per-iteration colsum slices (RED targets)
__device__ __nv_bfloat16 g_Ebf[(size_t)D * T];    // bf16 copy of E (iters 2..N)
__device__ unsigned int g_count[N_ITERS + 1];

// ---------- f32x2 helpers ----------
__device__ __forceinline__ unsigned long long fma2(unsigned long long a,
                                                   unsigned long long b,
                                                   unsigned long long c) {
    unsigned long long d;
    asm("fma.rn.f32x2 %0, %1, %2, %3;" : "=l"(d) : "l"(a), "l"(b), "l"(c));
    return d;
}
__device__ __forceinline__ unsigned long long add2(unsigned long long a,
                                                   unsigned long long b) {
    unsigned long long d;
    asm("add.rn.f32x2 %0, %1, %2;" : "=l"(d) : "l"(a), "l"(b));
    return d;
}
__device__ __forceinline__ float f2lo(unsigned long long x) {
    return __uint_as_float((unsigned int)x);
}
__device__ __forceinline__ float f2hi(unsigned long long x) {
    return __uint_as_float((unsigned int)(x >> 32));
}
__device__ __forceinline__ unsigned long long packf2(float lo, float hi) {
    return ((unsigned long long)__float_as_uint(hi) << 32) |
           (unsigned long long)__float_as_uint(lo);
}
// bf16x2 (lo=col j, hi=col j+1) -> packed f32x2 via 2x PRMT
__device__ __forceinline__ unsigned long long bf2_to_f2(unsigned int u) {
    unsigned int lo = __byte_perm(u, 0, 0x1044);   // bf_lo << 16
    unsigned int hi = __byte_perm(u, 0, 0x3244);   // bf_hi << 16
    return ((unsigned long long)hi << 32) | lo;
}
__device__ __forceinline__ float sgnf(float x) {
    return (float)((x > 0.0f) - (x < 0.0f));
}

// ---------- init: zero colsum slices + counters, seed optimizer state ----------
__global__ void init_kernel(const float* __restrict__ Binit) {
    int i = blockIdx.x * blockDim.x + threadIdx.x;
    // zero g_colsum via float4 grid-stride
    float4 z = make_float4(0.f, 0.f, 0.f, 0.f);
    const int n4 = (N_ITERS + 1) * T / 4;   // 550000/4 divisible
    for (int v = i; v < n4; v += gridDim.x * blockDim.x)
        reinterpret_cast<float4*>(g_colsum)[v] = z;
    if (i <= N_ITERS) g_count[i] = 0u;
    if (i < D * K) {
        float b = Binit[i];
        g_P[i] = b;
        g_B[i] = b;     // iteration 1 loss sees raw P
        g_M[i] = 0.0f;
        g_V[i] = 0.0f;
    }
}

// ---------- fused heavy + argmax + update ----------
// FIRST=true: reads fp32 E, also writes bf16 copy. FIRST=false: reads bf16 copy.
template <bool FIRST>
__global__ __launch_bounds__(HK_THREADS, 2)
void heavy_kernel(const float* __restrict__ E, const float* __restrict__ A,
                  float* __restrict__ outB, int it) {
    // Bt[k][r]: -B[chunk*64+r][k], lane-duplicated into both f32x2 halves (8 KB)
    __shared__ unsigned long long sBt[K * CHUNK_ROWS];
    __shared__ unsigned long long s_wmax[HK_THREADS / 32];
    __shared__ float sA[K];
    __shared__ float sColabs[K];
    __shared__ int sJstar, sKstar, sIsLast;

    const int tile = blockIdx.x;
    const int chunk = blockIdx.y;
    const int tid = threadIdx.x;

    for (int idx = tid; idx < K * CHUNK_ROWS; idx += HK_THREADS) {
        int k = idx & (K - 1);
        int r = idx >> 4;
        float b = -g_B[(chunk * CHUNK_ROWS + r) * K + k];
        unsigned int ub = __float_as_uint(b);
        sBt[k * CHUNK_ROWS + r] = ((unsigned long long)ub << 32) | (unsigned long long)ub;
    }
    __syncthreads();

    const int j0 = tile * TILE_COLS + tid * CPT;
    const int row0 = chunk * CHUNK_ROWS;

    if (j0 < T) {
        // A[k, j0..j0+3] into registers (fp32, 16B aligned)
        unsigned long long a01[K], a23[K];
#pragma unroll
        for (int k = 0; k < K; k++) {
            ulonglong2 av = *reinterpret_cast<const ulonglong2*>(A + k * T + j0);
            a01[k] = av.x;
            a23[k] = av.y;
        }

        unsigned long long cs01 = 0ull, cs23 = 0ull;

        if (FIRST) {
            const float* ep = E + (long long)row0 * T + j0;
            __nv_bfloat16* bp_out = g_Ebf + (long long)row0 * T + j0;
#pragma unroll 1
            for (int rb = 0; rb < NRB; rb++) {
                unsigned long long acc01[ROWS_REG], acc23[ROWS_REG];
#pragma unroll
                for (int r = 0; r < ROWS_REG; r++) {
                    float4 ev = *reinterpret_cast<const float4*>(ep + r * T);
                    acc01[r] = packf2(ev.x, ev.y);
                    acc23[r] = packf2(ev.z, ev.w);
                    unsigned int p01, p23;
                    asm("cvt.rn.bf16x2.f32 %0, %1, %2;" : "=r"(p01) : "f"(ev.y), "f"(ev.x));
                    asm("cvt.rn.bf16x2.f32 %0, %1, %2;" : "=r"(p23) : "f"(ev.w), "f"(ev.z));
                    uint2 st; st.x = p01; st.y = p23;
                    *reinterpret_cast<uint2*>(bp_out + r * T) = st;
                }
                ep += ROWS_REG * T;
                bp_out += ROWS_REG * T;

                const unsigned long long* bb = &sBt[rb * ROWS_REG];
                ulonglong2 b01 = *reinterpret_cast<const ulonglong2*>(bb);
                ulonglong2 b23 = *reinterpret_cast<const ulonglong2*>(bb + 2);
#pragma unroll
                for (int k = 0; k < K; k++) {
                    ulonglong2 nb01, nb23;
                    if (k + 1 < K) {
                        nb01 = *reinterpret_cast<const ulonglong2*>(bb + (k + 1) * CHUNK_ROWS);
                        nb23 = *reinterpret_cast<const ulonglong2*>(bb + (k + 1) * CHUNK_ROWS + 2);
                    }
                    acc01[0] = fma2(b01.x, a01[k], acc01[0]);
                    acc23[0] = fma2(b01.x, a23[k], acc23[0]);
                    acc01[1] = fma2(b01.y, a01[k], acc01[1]);
                    acc23[1] = fma2(b01.y, a23[k], acc23[1]);
                    acc01[2] = fma2(b23.x, a01[k], acc01[2]);
                    acc23[2] = fma2(b23.x, a23[k], acc23[2]);
                    acc01[3] = fma2(b23.y, a01[k], acc01[3]);
                    acc23[3] = fma2(b23.y, a23[k], acc23[3]);
                    b01 = nb01; b23 = nb23;
                }
#pragma unroll
                for (int r = 0; r < ROWS_REG; r++) {
                    cs01 = add2(cs01, acc01[r] & ABS2_MASK);
                    cs23 = add2(cs23, acc23[r] & ABS2_MASK);
                }
            }
        } else {
            const __nv_bfloat16* ep = g_Ebf + (long long)row0 * T + j0;
            uint2 e[ROWS_REG], en[ROWS_REG];
#pragma unroll
            for (int r = 0; r < ROWS_REG; r++)
                e[r] = *reinterpret_cast<const uint2*>(ep + r * T);

#pragma unroll 1
            for (int rb = 0; rb < NRB; rb++) {
                if (rb + 1 < NRB) {
                    const __nv_bfloat16* epn = ep + ROWS_REG * T;
#pragma unroll
                    for (int r = 0; r < ROWS_REG; r++)
                        en[r] = *reinterpret_cast<const uint2*>(epn + r * T);
                }
                ep += ROWS_REG * T;

                unsigned long long acc01[ROWS_REG], acc23[ROWS_REG];
#pragma unroll
                for (int r = 0; r < ROWS_REG; r++) {
                    acc01[r] = bf2_to_f2(e[r].x);
                    acc23[r] = bf2_to_f2(e[r].y);
                }
                const unsigned long long* bb = &sBt[rb * ROWS_REG];
                ulonglong2 b01 = *reinterpret_cast<const ulonglong2*>(bb);
                ulonglong2 b23 = *reinterpret_cast<const ulonglong2*>(bb + 2);
#pragma unroll
                for (int k = 0; k < K; k++) {
                    ulonglong2 nb01, nb23;
                    if (k + 1 < K) {
                        nb01 = *reinterpret_cast<const ulonglong2*>(bb + (k + 1) * CHUNK_ROWS);
                        nb23 = *reinterpret_cast<const ulonglong2*>(bb + (k + 1) * CHUNK_ROWS + 2);
                    }
                    acc01[0] = fma2(b01.x, a01[k], acc01[0]);
                    acc23[0] = fma2(b01.x, a23[k], acc23[0]);
                    acc01[1] = fma2(b01.y, a01[k], acc01[1]);
                    acc23[1] = fma2(b01.y, a23[k], acc23[1]);
                    acc01[2] = fma2(b23.x, a01[k], acc01[2]);
                    acc23[2] = fma2(b23.x, a23[k], acc23[2]);
                    acc01[3] = fma2(b23.y, a01[k], acc01[3]);
                    acc23[3] = fma2(b23.y, a23[k], acc23[3]);
                    b01 = nb01; b23 = nb23;
                }
#pragma unroll
                for (int r = 0; r < ROWS_REG; r++) {
                    cs01 = add2(cs01, acc01[r] & ABS2_MASK);
                    cs23 = add2(cs23, acc23[r] & ABS2_MASK);
                    e[r] = en[r];
                }
            }
        }

        // accumulate into this iteration's colsum slice (RED.F32, no return)
        float* csl = g_colsum + it * T + j0;
        atomicAdd(csl + 0, f2lo(cs01));
        atomicAdd(csl + 1, f2hi(cs01));
        atomicAdd(csl + 2, f2lo(cs23));
        atomicAdd(csl + 3, f2hi(cs23));
    }

    // ---------- last-block epilogue (threadfence-reduction pattern) ----------
    __threadfence();
    __syncthreads();
    if (tid == 0) {
        unsigned int ticket = atomicAdd(&g_count[it], 1u);
        sIsLast = (ticket == GRID_BLOCKS - 1);
    }
    __syncthreads();
    if (!sIsLast) return;

    // argmax over colsum slice (float4, coalesced)
    {
        const float4* cs4 = reinterpret_cast<const float4*>(g_colsum + it * T);
        unsigned long long best = 0ull;
        for (int v = tid; v < T / 4; v += HK_THREADS) {
            float4 val = cs4[v];
            int j = 4 * v;
            // values >= 0 -> float bits order-preserving; tie-break toward smaller j
            unsigned long long k0 =
                ((unsigned long long)__float_as_uint(val.x) << 32) | (unsigned int)(T - 1 - j);
            unsigned long long k1 =
                ((unsigned long long)__float_as_uint(val.y) << 32) | (unsigned int)(T - 2 - j);
            unsigned long long k2 =
                ((unsigned long long)__float_as_uint(val.z) << 32) | (unsigned int)(T - 3 - j);
            unsigned long long k3 =
                ((unsigned long long)__float_as_uint(val.w) << 32) | (unsigned int)(T - 4 - j);
            if (k1 > k0) k0 = k1;
            if (k3 > k2) k2 = k3;
            if (k2 > k0) k0 = k2;
            if (k0 > best) best = k0;
        }
#pragma unroll
        for (int o = 16; o; o >>= 1) {
            unsigned long long other = __shfl_down_sync(0xffffffffu, best, o);
            if (other > best) best = other;
        }
        if ((tid & 31) == 0) s_wmax[tid >> 5] = best;
        __syncthreads();
        if (tid == 0) {
            unsigned long long b = s_wmax[0];
#pragma unroll
            for (int w = 1; w < HK_THREADS / 32; w++)
                if (s_wmax[w] > b) b = s_wmax[w];
            sJstar = T - 1 - (int)(b & 0xffffffffu);
        }
        __syncthreads();
    }
    const int jstar = sJstar;

    // stage A[:, j*]
    if (tid < K) sA[tid] = A[tid * T + jstar];

    // column abs-sums of B: warp w handles columns w and w+8
    {
        int w = tid >> 5, lane = tid & 31;
#pragma unroll
        for (int c = w; c < K; c += HK_THREADS / 32) {
            float s = 0.0f;
            for (int i = lane; i < D; i += 32) s += fabsf(g_B[i * K + c]);
#pragma unroll
            for (int o = 16; o; o >>= 1) s += __shfl_down_sync(0xffffffffu, s, o);
            if (lane == 0) sColabs[c] = s;
        }
    }
    __syncthreads();
    if (tid == 0) {
        int ks = 0;
        float bv = sColabs[0];
#pragma unroll
        for (int k = 1; k < K; k++)
            if (sColabs[k] > bv) { bv = sColabs[k]; ks = k; }
        sKstar = ks;
    }

    // residual sign for rows tid, tid+256 at column j* (exact fp32 from original E)
    float si[2];
#pragma unroll
    for (int h = 0; h < 2; h++) {
        int row = tid + h * HK_THREADS;
        float r = E[(long long)row * T + jstar];
#pragma unroll
        for (int k = 0; k < K; k++) r -= g_B[row * K + k] * sA[k];
        si[h] = sgnf(r);
    }
    __syncthreads();            // sKstar ready; g_B reads complete before writes
    const int kstar = sKstar;

    // gradient + shrink chain + Adam + new B = shrink(P)
    {
        float tf = (float)it;
        float bc1 = 1.0f - powf(BETA1_F, tf);
        float bc2 = 1.0f - powf(BETA2_F, tf);
#pragma unroll
        for (int h = 0; h < 2; h++) {
            int row = tid + h * HK_THREADS;
#pragma unroll
            for (int k = 0; k < K; k++) {
                int idx = row * K + k;
                float bu = g_B[idx];
                float g = -si[h] * sA[k];
                if (k == kstar) g += LAMBDA1_F * sgnf(bu);
                float p = g_P[idx];
                if (it >= 2) g *= sgnf(p) * sgnf(p - SHRINK_C);   // d shrink / dP
                float m = BETA1_F * g_M[idx] + ONE_M_B1 * g;
                float v = BETA2_F * g_V[idx] + ONE_M_B2 * g * g;
                g_M[idx] = m;
                g_V[idx] = v;
                float mh = m / bc1;
                float vh = v / bc2;
                p = p - LR_F * mh / (sqrtf(vh) + ADAM_EPS_F);
                g_P[idx] = p;
                float bn = sgnf(p) * fmaxf(0.0f, fabsf(p - SHRINK_C));
                g_B[idx] = bn;
                if (it == N_ITERS) outB[idx] = bn;
            }
        }
    }
}

extern "C" void kernel_launch(void* const* d_in, const int* in_sizes, int n_in,
                              void* d_out, int out_size) {
    (void)in_sizes; (void)n_in; (void)out_size;
    const float* E  = (const float*)d_in[0];   // embedding (512, 50000)
    const float* B0 = (const float*)d_in[1];   // basis_init (512, 16)
    const float* A  = (const float*)d_in[2];   // activation_init (16, 50000)
    float* out = (float*)d_out;                // [shrink(P) (512x16) | A (16x50000)]

    // A is constant in the reference (optimizer_act never steps) — copy once
    cudaMemcpyAsync(out + D * K, (const void*)A, (size_t)K * T * sizeof(float),
                    cudaMemcpyDeviceToDevice);

    init_kernel<<<592, 256>>>(B0);   // 592*256 threads: zeroes 137.5K float4 in one stride

    dim3 grid(NTILE, NCHUNK);
    for (int it = 1; it <= N_ITERS; ++it) {
        if (it == 1)
            heavy_kernel<true><<<grid, HK_THREADS>>>(E, A, out, it);
        else
            heavy_kernel<false><<<grid, HK_THREADS>>>(E, A, out, it);
    }
}